// round 3
// baseline (speedup 1.0000x reference)
#include <cuda_runtime.h>
#include <cuda_bf16.h>
#include <math.h>
#include <stdint.h>

#define NN 20000
#define ETOT 150000
#define LPART 75000
#define FINC 256
#define HC 512
#define H2C 1024

// ---------------- static device scratch (no runtime alloc allowed) ----------------
__device__ float g_sf[NN * HC];
__device__ float g_df[NN * HC];
__device__ float g_out[NN * HC];
__device__ float g_h[NN * H2C];
__device__ float g_y[NN * HC];
__device__ float g_x1[NN * HC];
__device__ int g_rowptr[2][NN + 1];
__device__ int g_cursor[2][NN];
__device__ int g_eidx[2][LPART];

// ---------------- small utility kernels ----------------
__global__ void k_zero_int(int* p, int n) {
    int i = blockIdx.x * blockDim.x + threadIdx.x;
    if (i < n) p[i] = 0;
}

__global__ void k_count_deg(const int* __restrict__ dst, int L, int* __restrict__ deg) {
    int i = blockIdx.x * blockDim.x + threadIdx.x;
    if (i < L) atomicAdd(&deg[dst[i]], 1);
}

// single-block inclusive scan over n counts -> exclusive rowptr (n+1)
__global__ void k_scan(const int* __restrict__ deg, int* __restrict__ rowptr, int n) {
    __shared__ int sbuf[1024];
    __shared__ int carry;
    int t = threadIdx.x;
    if (t == 0) { carry = 0; rowptr[0] = 0; }
    __syncthreads();
    for (int base = 0; base < n; base += 1024) {
        int v = (base + t < n) ? deg[base + t] : 0;
        sbuf[t] = v;
        __syncthreads();
        for (int off = 1; off < 1024; off <<= 1) {
            int nv = (t >= off) ? sbuf[t - off] : 0;
            __syncthreads();
            sbuf[t] += nv;
            __syncthreads();
        }
        if (base + t < n) rowptr[base + t + 1] = carry + sbuf[t];
        __syncthreads();
        if (t == 0) carry += sbuf[1023];
        __syncthreads();
    }
}

__global__ void k_copy_int(const int* __restrict__ a, int* __restrict__ b, int n) {
    int i = blockIdx.x * blockDim.x + threadIdx.x;
    if (i < n) b[i] = a[i];
}

__global__ void k_scatter(const int* __restrict__ dst, int L, int* __restrict__ cursor,
                          int* __restrict__ eidx) {
    int i = blockIdx.x * blockDim.x + threadIdx.x;
    if (i < L) {
        int pos = atomicAdd(&cursor[dst[i]], 1);
        eidx[pos] = i;
    }
}

// deterministic edge order within each bucket (insertion sort; avg degree ~3.75)
__global__ void k_sort_buckets(const int* __restrict__ rowptr, int* __restrict__ eidx) {
    int node = blockIdx.x * blockDim.x + threadIdx.x;
    if (node >= NN) return;
    int a = rowptr[node], b = rowptr[node + 1];
    for (int i = a + 1; i < b; i++) {
        int key = eidx[i];
        int j = i - 1;
        while (j >= a && eidx[j] > key) { eidx[j + 1] = eidx[j]; j--; }
        eidx[j + 1] = key;
    }
}

__global__ void k_leaky(const float* __restrict__ y, float* __restrict__ x1, int n) {
    int i = blockIdx.x * blockDim.x + threadIdx.x;
    if (i < n) {
        float v = y[i];
        x1[i] = v > 0.f ? v : 0.01f * v;
    }
}

// ---------------- fused per-node edge softmax aggregation ----------------
__global__ __launch_bounds__(128) void k_agg(
    const float* __restrict__ sfeat, const float* __restrict__ dfeat,
    const float* __restrict__ We, const float* __restrict__ ea,
    const int* __restrict__ srcIdx, const int* __restrict__ rowptr,
    const int* __restrict__ eidx, float* __restrict__ outp)
{
    __shared__ float wsh[HC];
    int t = threadIdx.x;
    for (int i = t; i < HC; i += 128) wsh[i] = We[i];
    __syncthreads();
    int warp = t >> 5, lane = t & 31;
    int node = blockIdx.x * 4 + warp;
    if (node >= NN) return;

    float wv[16];
#pragma unroll
    for (int j = 0; j < 16; j++) wv[j] = wsh[lane + 32 * j];

    float m[16], s[16], tt[16];
#pragma unroll
    for (int j = 0; j < 16; j++) { m[j] = -INFINITY; s[j] = 0.f; tt[j] = 0.f; }

    int e0 = rowptr[node], e1 = rowptr[node + 1];
    for (int e = e0; e < e1; e++) {
        int eid = eidx[e];
        int sidx = srcIdx[eid];
        float a = ea[eid];
        const float* row = sfeat + (size_t)sidx * HC;
#pragma unroll
        for (int j = 0; j < 16; j++) {
            float msg = fmaxf(row[lane + 32 * j] + a * wv[j], 0.f) + 1e-7f;
            float mn = fmaxf(m[j], msg);
            float scale = __expf(m[j] - mn);
            float p = __expf(msg - mn);
            s[j] = s[j] * scale + p;
            tt[j] = tt[j] * scale + msg * p;
            m[j] = mn;
        }
    }
    float* orow = outp + (size_t)node * HC;
    const float* drow = dfeat + (size_t)node * HC;
#pragma unroll
    for (int j = 0; j < 16; j++)
        orow[lane + 32 * j] = tt[j] / (s[j] + 1e-16f) + drow[lane + 32 * j];
}

// ---------------- TF32 tensor-core GEMM (NT), cp.async 4-stage pipeline -----------
// C[M,Nc] = A[M,K] @ B[Nc,K]^T ; block tile 128x128x16, 256 threads, 8 warps,
// warp tile 64x32 (4x4 m16n8k8 atoms). smem stores raw fp32; tf32 cvt at frag load.
#define BM 128
#define BN 128
#define BK 16
#define BKW 20          // padded row stride (words) -> conflict-free
#define STAGES 4
#define TILE_WORDS (BM * BKW)
#define SMEM_BYTES (STAGES * TILE_WORDS * 2 * 4)

__device__ __forceinline__ uint32_t f2tf(float f) {
    uint32_t r;
    asm("cvt.rna.tf32.f32 %0, %1;" : "=r"(r) : "f"(f));
    return r;
}

__device__ __forceinline__ void mma_tf32(float* c, const uint32_t* a, uint32_t b0, uint32_t b1) {
    asm volatile(
        "mma.sync.aligned.m16n8k8.row.col.f32.tf32.tf32.f32 "
        "{%0,%1,%2,%3}, {%4,%5,%6,%7}, {%8,%9}, {%0,%1,%2,%3};"
        : "+f"(c[0]), "+f"(c[1]), "+f"(c[2]), "+f"(c[3])
        : "r"(a[0]), "r"(a[1]), "r"(a[2]), "r"(a[3]), "r"(b0), "r"(b1));
}

__device__ __forceinline__ void cp16(uint32_t saddr, const void* gaddr, int srcbytes) {
    asm volatile("cp.async.cg.shared.global [%0], [%1], 16, %2;"
                 :: "r"(saddr), "l"(gaddr), "r"(srcbytes));
}

__global__ __launch_bounds__(256, 2) void k_mma_nt(
    const float* __restrict__ A, const float* __restrict__ B, float* __restrict__ C,
    int M, int Ncols, int K, int mode,
    const float* __restrict__ gv, const float* __restrict__ bv,
    const float* __restrict__ mv, const float* __restrict__ vv, int accum)
{
    extern __shared__ float sm[];
    float* As = sm;                          // [STAGES][BM][BKW]
    float* Bs = sm + STAGES * TILE_WORDS;    // [STAGES][BN][BKW]
    uint32_t sAs = (uint32_t)__cvta_generic_to_shared(As);
    uint32_t sBs = (uint32_t)__cvta_generic_to_shared(Bs);

    int tid = threadIdx.x;
    int tileM = blockIdx.y * BM, tileN = blockIdx.x * BN;
    int warp = tid >> 5, lane = tid & 31;
    int g8 = lane >> 2, t4 = lane & 3;
    int wm = (warp & 1) * 64;
    int wn = (warp >> 1) * 32;

    // cp.async staging: 2 chunks (16B) per thread per matrix; 512 chunks = 128 rows x 4
    int ch0 = tid * 2;
    int r0c = ch0 >> 2, c0c = (ch0 & 3) * 4;
    int r1c = (ch0 + 1) >> 2, c1c = ((ch0 + 1) & 3) * 4;
    int predA0 = (tileM + r0c) < M ? 16 : 0;
    int predA1 = (tileM + r1c) < M ? 16 : 0;
    const float* Abase = A + (size_t)(tileM + r0c) * K + c0c;
    const float* Abase1 = A + (size_t)(tileM + r1c) * K + c1c;
    const float* Bbase = B + (size_t)(tileN + r0c) * K + c0c;
    const float* Bbase1 = B + (size_t)(tileN + r1c) * K + c1c;
    uint32_t sA0 = sAs + (uint32_t)((r0c * BKW + c0c) * 4);
    uint32_t sA1 = sAs + (uint32_t)((r1c * BKW + c1c) * 4);
    uint32_t sB0 = sBs + (uint32_t)((r0c * BKW + c0c) * 4);
    uint32_t sB1 = sBs + (uint32_t)((r1c * BKW + c1c) * 4);

    float acc[4][4][4];
#pragma unroll
    for (int i = 0; i < 4; i++)
#pragma unroll
        for (int j = 0; j < 4; j++)
#pragma unroll
            for (int r = 0; r < 4; r++) acc[i][j][r] = 0.f;

    int ntiles = K / BK;

#define ISSUE(tile, stage)                                                        \
    do {                                                                          \
        int kb_ = (tile) * BK;                                                    \
        uint32_t so_ = (uint32_t)((stage) * TILE_WORDS * 4);                      \
        cp16(sA0 + so_, Abase + kb_, predA0);                                     \
        cp16(sA1 + so_, Abase1 + kb_, predA1);                                    \
        cp16(sB0 + so_, Bbase + kb_, 16);                                         \
        cp16(sB1 + so_, Bbase1 + kb_, 16);                                        \
    } while (0)

    // prologue: STAGES-1 tiles in flight
#pragma unroll
    for (int s = 0; s < STAGES - 1; s++) {
        if (s < ntiles) ISSUE(s, s);
        asm volatile("cp.async.commit_group;");
    }

    for (int t = 0; t < ntiles; t++) {
        asm volatile("cp.async.wait_group %0;" :: "n"(STAGES - 2));
        __syncthreads();

        int nt = t + STAGES - 1;
        if (nt < ntiles) ISSUE(nt, nt & (STAGES - 1));
        asm volatile("cp.async.commit_group;");

        const float* as = As + (t & (STAGES - 1)) * TILE_WORDS;
        const float* bs = Bs + (t & (STAGES - 1)) * TILE_WORDS;

#pragma unroll
        for (int kk = 0; kk < BK / 8; kk++) {
            int kb = kk * 8;
            uint32_t af[4][4];
#pragma unroll
            for (int i = 0; i < 4; i++) {
                int rr = wm + i * 16 + g8;
                af[i][0] = f2tf(as[rr * BKW + kb + t4]);
                af[i][1] = f2tf(as[(rr + 8) * BKW + kb + t4]);
                af[i][2] = f2tf(as[rr * BKW + kb + t4 + 4]);
                af[i][3] = f2tf(as[(rr + 8) * BKW + kb + t4 + 4]);
            }
#pragma unroll
            for (int j = 0; j < 4; j++) {
                int n0 = wn + j * 8 + g8;
                uint32_t bf0 = f2tf(bs[n0 * BKW + kb + t4]);
                uint32_t bf1 = f2tf(bs[n0 * BKW + kb + t4 + 4]);
#pragma unroll
                for (int i = 0; i < 4; i++) mma_tf32(acc[i][j], af[i], bf0, bf1);
            }
        }
    }

    // ---- epilogue ----
    float cs[4][2], cb[4][2], cm[4][2];
    if (mode == 1) {
#pragma unroll
        for (int j = 0; j < 4; j++) {
            int c = tileN + wn + j * 8 + t4 * 2;
#pragma unroll
            for (int q = 0; q < 2; q++) {
                cs[j][q] = gv[c + q] * rsqrtf(vv[c + q] + 1e-5f);
                cb[j][q] = bv[c + q];
                cm[j][q] = mv[c + q];
            }
        }
    }

#pragma unroll
    for (int i = 0; i < 4; i++) {
#pragma unroll
        for (int half = 0; half < 2; half++) {
            int r = tileM + wm + i * 16 + g8 + half * 8;
            if (r >= M) continue;
            float* crow = C + (size_t)r * Ncols;
#pragma unroll
            for (int j = 0; j < 4; j++) {
                int c = tileN + wn + j * 8 + t4 * 2;
                float v0 = acc[i][j][half * 2 + 0];
                float v1 = acc[i][j][half * 2 + 1];
                if (mode == 1) {
                    v0 = fmaxf((v0 - cm[j][0]) * cs[j][0] + cb[j][0], 0.f);
                    v1 = fmaxf((v1 - cm[j][1]) * cs[j][1] + cb[j][1], 0.f);
                }
                if (accum) {
                    float2 old = *(const float2*)(crow + c);
                    v0 += old.x;
                    v1 += old.y;
                }
                *(float2*)(crow + c) = make_float2(v0, v1);
            }
        }
    }
}

// ---------------- host orchestration ----------------
extern "C" void kernel_launch(void* const* d_in, const int* in_sizes, int n_in,
                              void* d_out, int out_size) {
    const float* x  = (const float*)d_in[0];
    const int*   ei = (const int*)d_in[1];
    const float* ea = (const float*)d_in[2];
    int base = 3;
    if (n_in > 19) base = 3 + (n_in - 19);  // skip len0/len1 scalars if present
    const float* l0_src  = (const float*)d_in[base + 0];
    const float* l0_dst  = (const float*)d_in[base + 1];
    const float* l0_edge = (const float*)d_in[base + 2];
    const float* l0_w1   = (const float*)d_in[base + 3];
    const float* l0_g    = (const float*)d_in[base + 4];
    const float* l0_b    = (const float*)d_in[base + 5];
    const float* l0_m    = (const float*)d_in[base + 6];
    const float* l0_v    = (const float*)d_in[base + 7];
    const float* l0_w2   = (const float*)d_in[base + 8];
    const float* l1_edge = (const float*)d_in[base + 9];
    const float* l1_w1   = (const float*)d_in[base + 10];
    const float* l1_g    = (const float*)d_in[base + 11];
    const float* l1_b    = (const float*)d_in[base + 12];
    const float* l1_m    = (const float*)d_in[base + 13];
    const float* l1_v    = (const float*)d_in[base + 14];
    const float* l1_w2   = (const float*)d_in[base + 15];
    float* out = (float*)d_out;

    float *sf, *df, *ob, *hb, *yb, *x1b;
    int *rowptr, *cursor, *eidx;
    cudaGetSymbolAddress((void**)&sf, g_sf);
    cudaGetSymbolAddress((void**)&df, g_df);
    cudaGetSymbolAddress((void**)&ob, g_out);
    cudaGetSymbolAddress((void**)&hb, g_h);
    cudaGetSymbolAddress((void**)&yb, g_y);
    cudaGetSymbolAddress((void**)&x1b, g_x1);
    cudaGetSymbolAddress((void**)&rowptr, g_rowptr);
    cudaGetSymbolAddress((void**)&cursor, g_cursor);
    cudaGetSymbolAddress((void**)&eidx, g_eidx);

    cudaFuncSetAttribute(k_mma_nt, cudaFuncAttributeMaxDynamicSharedMemorySize, SMEM_BYTES);

    const int offs[2] = {0, LPART};

    // ---- build CSR-by-dst for both edge partitions ----
    for (int p = 0; p < 2; p++) {
        int* rp = rowptr + p * (NN + 1);
        int* cu = cursor + p * NN;
        int* ex = eidx + p * LPART;
        const int* dstp = ei + ETOT + offs[p];
        k_zero_int<<<(NN + 255) / 256, 256>>>(cu, NN);
        k_count_deg<<<(LPART + 255) / 256, 256>>>(dstp, LPART, cu);
        k_scan<<<1, 1024>>>(cu, rp, NN);
        k_copy_int<<<(NN + 255) / 256, 256>>>(rp, cu, NN);
        k_scatter<<<(LPART + 255) / 256, 256>>>(dstp, LPART, cu, ex);
        k_sort_buckets<<<(NN + 127) / 128, 128>>>(rp, ex);
    }

    dim3 blk(256);
    int gy = (NN + BM - 1) / BM;  // 157
    dim3 g512(HC / BN, gy), g1024(H2C / BN, gy);

    // ---- layer 0 ----
    for (int l = 0; l < 2; l++) {
        k_mma_nt<<<g512, blk, SMEM_BYTES>>>(x, l0_src + (size_t)l * HC * FINC, sf,
                                NN, HC, FINC, 0, nullptr, nullptr, nullptr, nullptr, 0);
        k_mma_nt<<<g512, blk, SMEM_BYTES>>>(x, l0_dst + (size_t)l * HC * FINC, df,
                                NN, HC, FINC, 0, nullptr, nullptr, nullptr, nullptr, 0);
        k_agg<<<(NN + 3) / 4, 128>>>(sf, df, l0_edge + (size_t)l * HC, ea + offs[l],
                                     ei + offs[l], rowptr + l * (NN + 1),
                                     eidx + l * LPART, ob);
        k_mma_nt<<<g1024, blk, SMEM_BYTES>>>(ob, l0_w1 + (size_t)l * H2C * HC, hb,
                                 NN, H2C, HC, 1,
                                 l0_g + l * H2C, l0_b + l * H2C,
                                 l0_m + l * H2C, l0_v + l * H2C, 0);
        k_mma_nt<<<g512, blk, SMEM_BYTES>>>(hb, l0_w2 + (size_t)l * HC * H2C, yb,
                                NN, HC, H2C, 0, nullptr, nullptr, nullptr, nullptr, l > 0);
    }

    k_leaky<<<(NN * HC + 255) / 256, 256>>>(yb, x1b, NN * HC);

    // ---- layer 1 (no src/dst projections: sf = df = x1) ----
    for (int l = 0; l < 2; l++) {
        k_agg<<<(NN + 3) / 4, 128>>>(x1b, x1b, l1_edge + (size_t)l * HC, ea + offs[l],
                                     ei + offs[l], rowptr + l * (NN + 1),
                                     eidx + l * LPART, ob);
        k_mma_nt<<<g1024, blk, SMEM_BYTES>>>(ob, l1_w1 + (size_t)l * H2C * HC, hb,
                                 NN, H2C, HC, 1,
                                 l1_g + l * H2C, l1_b + l * H2C,
                                 l1_m + l * H2C, l1_v + l * H2C, 0);
        k_mma_nt<<<g512, blk, SMEM_BYTES>>>(hb, l1_w2 + (size_t)l * HC * H2C, out,
                                NN, HC, H2C, 0, nullptr, nullptr, nullptr, nullptr, l > 0);
    }
}

// round 6
// speedup vs baseline: 1.6850x; 1.6850x over previous
#include <cuda_runtime.h>
#include <cuda_fp16.h>
#include <math.h>
#include <stdint.h>

#define NN 20000
#define ETOT 150000
#define LPART 75000
#define FINC 256
#define HC 512
#define H2C 1024

// ---------------- static device scratch ----------------
__device__ float g_sf[NN * HC];
__device__ float g_df[NN * HC];
__device__ float g_y[NN * HC];
__device__ float g_x1[NN * HC];
__device__ __half g_xh[NN * FINC];
__device__ __half g_ob[NN * HC];
__device__ __half g_hb[NN * H2C];
__device__ __half g_w0s[2 * HC * FINC], g_w0d[2 * HC * FINC];
__device__ __half g_w01[2 * H2C * HC], g_w02[2 * HC * H2C];
__device__ __half g_w11[2 * H2C * HC], g_w12[2 * HC * H2C];
__device__ int g_rowptr[2][NN + 1];
__device__ int g_cursor[2][NN];
__device__ int g_eidx[2][LPART];

// ---------------- small utility kernels ----------------
__global__ void k_zero_int(int* p, int n) {
    int i = blockIdx.x * blockDim.x + threadIdx.x;
    if (i < n) p[i] = 0;
}

__global__ void k_count_deg(const int* __restrict__ dst, int L, int* __restrict__ deg) {
    int i = blockIdx.x * blockDim.x + threadIdx.x;
    if (i < L) atomicAdd(&deg[dst[i]], 1);
}

__global__ void k_scan(const int* __restrict__ deg, int* __restrict__ rowptr, int n) {
    __shared__ int sbuf[1024];
    __shared__ int carry;
    int t = threadIdx.x;
    if (t == 0) { carry = 0; rowptr[0] = 0; }
    __syncthreads();
    for (int base = 0; base < n; base += 1024) {
        int v = (base + t < n) ? deg[base + t] : 0;
        sbuf[t] = v;
        __syncthreads();
        for (int off = 1; off < 1024; off <<= 1) {
            int nv = (t >= off) ? sbuf[t - off] : 0;
            __syncthreads();
            sbuf[t] += nv;
            __syncthreads();
        }
        if (base + t < n) rowptr[base + t + 1] = carry + sbuf[t];
        __syncthreads();
        if (t == 0) carry += sbuf[1023];
        __syncthreads();
    }
}

__global__ void k_copy_int(const int* __restrict__ a, int* __restrict__ b, int n) {
    int i = blockIdx.x * blockDim.x + threadIdx.x;
    if (i < n) b[i] = a[i];
}

__global__ void k_scatter(const int* __restrict__ dst, int L, int* __restrict__ cursor,
                          int* __restrict__ eidx) {
    int i = blockIdx.x * blockDim.x + threadIdx.x;
    if (i < L) {
        int pos = atomicAdd(&cursor[dst[i]], 1);
        eidx[pos] = i;
    }
}

__global__ void k_sort_buckets(const int* __restrict__ rowptr, int* __restrict__ eidx) {
    int node = blockIdx.x * blockDim.x + threadIdx.x;
    if (node >= NN) return;
    int a = rowptr[node], b = rowptr[node + 1];
    for (int i = a + 1; i < b; i++) {
        int key = eidx[i];
        int j = i - 1;
        while (j >= a && eidx[j] > key) { eidx[j + 1] = eidx[j]; j--; }
        eidx[j + 1] = key;
    }
}

__global__ void k_leaky(const float* __restrict__ y, float* __restrict__ x1, int n) {
    int i = blockIdx.x * blockDim.x + threadIdx.x;
    if (i < n) {
        float v = y[i];
        x1[i] = v > 0.f ? v : 0.01f * v;
    }
}

__global__ void k_half(const float* __restrict__ s, __half* __restrict__ h, int n) {
    int i = blockIdx.x * blockDim.x + threadIdx.x;
    if (i < n) h[i] = __float2half(s[i]);
}

// ---------------- fused per-node edge softmax aggregation (fp16 out) -------------
__global__ __launch_bounds__(128) void k_agg(
    const float* __restrict__ sfeat, const float* __restrict__ dfeat,
    const float* __restrict__ We, const float* __restrict__ ea,
    const int* __restrict__ srcIdx, const int* __restrict__ rowptr,
    const int* __restrict__ eidx, __half* __restrict__ oh)
{
    __shared__ float wsh[HC];
    int t = threadIdx.x;
    for (int i = t; i < HC; i += 128) wsh[i] = We[i];
    __syncthreads();
    int warp = t >> 5, lane = t & 31;
    int node = blockIdx.x * 4 + warp;
    if (node >= NN) return;

    float wv[16];
#pragma unroll
    for (int j = 0; j < 16; j++) wv[j] = wsh[lane + 32 * j];

    float m[16], s[16], tt[16];
#pragma unroll
    for (int j = 0; j < 16; j++) { m[j] = -INFINITY; s[j] = 0.f; tt[j] = 0.f; }

    int e0 = rowptr[node], e1 = rowptr[node + 1];
    for (int e = e0; e < e1; e++) {
        int eid = eidx[e];
        int sidx = srcIdx[eid];
        float a = ea[eid];
        const float* row = sfeat + (size_t)sidx * HC;
#pragma unroll
        for (int j = 0; j < 16; j++) {
            float msg = fmaxf(row[lane + 32 * j] + a * wv[j], 0.f) + 1e-7f;
            float mn = fmaxf(m[j], msg);
            float scale = __expf(m[j] - mn);
            float p = __expf(msg - mn);
            s[j] = s[j] * scale + p;
            tt[j] = tt[j] * scale + msg * p;
            m[j] = mn;
        }
    }
    const float* drow = dfeat + (size_t)node * HC;
    __half* hrow = oh + (size_t)node * HC;
#pragma unroll
    for (int j = 0; j < 16; j++) {
        float v = tt[j] / (s[j] + 1e-16f) + drow[lane + 32 * j];
        hrow[lane + 32 * j] = __float2half(v);
    }
}

// ---------------- fp16 tensor-core GEMM (NT), cp.async 4-stage pipeline ----------
// C[M,Nc] = A[M,K] @ B[Nc,K]^T, A/B fp16, accum fp32.
// Block 128x128x32, 256 threads, warp tile 64x32 (4x4 m16n8k16 atoms).
// mode 0: fp32 out (+accum). mode 1: BN+ReLU -> fp16 out.
#define BM 128
#define BN 128
#define BK 32
#define BKH 40                      // padded row stride in halfs -> conflict-free
#define STG 4
#define TILE_B (BM * BKH * 2)       // 10240 bytes per matrix per stage
#define STAGE_B (2 * TILE_B)        // 20480
#define DSMEM (STG * STAGE_B)       // 81920

__device__ __forceinline__ void mma_f16(float* c, const uint32_t* a, uint32_t b0, uint32_t b1) {
    asm volatile(
        "mma.sync.aligned.m16n8k16.row.col.f32.f16.f16.f32 "
        "{%0,%1,%2,%3}, {%4,%5,%6,%7}, {%8,%9}, {%0,%1,%2,%3};"
        : "+f"(c[0]), "+f"(c[1]), "+f"(c[2]), "+f"(c[3])
        : "r"(a[0]), "r"(a[1]), "r"(a[2]), "r"(a[3]), "r"(b0), "r"(b1));
}

__device__ __forceinline__ void cp16(uint32_t saddr, const void* gaddr, int srcbytes) {
    asm volatile("cp.async.cg.shared.global [%0], [%1], 16, %2;"
                 :: "r"(saddr), "l"(gaddr), "r"(srcbytes));
}

__global__ __launch_bounds__(256, 2) void k_hgemm(
    const __half* __restrict__ A, const __half* __restrict__ B,
    int M, int K, int Ncols, int mode,
    const float* __restrict__ gv, const float* __restrict__ bv,
    const float* __restrict__ mv, const float* __restrict__ vv,
    float* __restrict__ Cf, __half* __restrict__ Ch, int accum)
{
    extern __shared__ __align__(128) char smc[];
    uint32_t sbase = (uint32_t)__cvta_generic_to_shared(smc);

    int tid = threadIdx.x;
    int tileM = blockIdx.y * BM, tileN = blockIdx.x * BN;
    int warp = tid >> 5, lane = tid & 31;
    int g8 = lane >> 2, t4 = lane & 3;
    int wm = (warp & 1) * 64;
    int wn = (warp >> 1) * 32;

    const __half* Ag = A + (size_t)tileM * K;
    const __half* Bg = B + (size_t)tileN * K;

    // staging map: 2 chunks (16B = 8 halfs) per thread per matrix
    int q0 = tid, q1 = tid + 256;
    int r0s = q0 >> 2, c0s = (q0 & 3) * 8;
    int r1s = q1 >> 2, c1s = (q1 & 3) * 8;
    int szA0 = (tileM + r0s) < M ? 16 : 0;
    int szA1 = (tileM + r1s) < M ? 16 : 0;
    uint32_t dA0 = sbase + (uint32_t)(r0s * (BKH * 2) + c0s * 2);
    uint32_t dA1 = sbase + (uint32_t)(r1s * (BKH * 2) + c1s * 2);
    uint32_t dB0 = dA0 + TILE_B;
    uint32_t dB1 = dA1 + TILE_B;

    float acc[4][4][4];
#pragma unroll
    for (int i = 0; i < 4; i++)
#pragma unroll
        for (int j = 0; j < 4; j++)
#pragma unroll
            for (int r = 0; r < 4; r++) acc[i][j][r] = 0.f;

    int nt = K / BK;

#define HISSUE(tile, stage)                                                     \
    do {                                                                        \
        int kb_ = (tile) * BK;                                                  \
        uint32_t so_ = (uint32_t)((stage) * STAGE_B);                           \
        cp16(dA0 + so_, Ag + (size_t)r0s * K + kb_ + c0s, szA0);                \
        cp16(dA1 + so_, Ag + (size_t)r1s * K + kb_ + c1s, szA1);                \
        cp16(dB0 + so_, Bg + (size_t)r0s * K + kb_ + c0s, 16);                  \
        cp16(dB1 + so_, Bg + (size_t)r1s * K + kb_ + c1s, 16);                  \
    } while (0)

#pragma unroll
    for (int s = 0; s < STG - 1; s++) {
        if (s < nt) HISSUE(s, s);
        asm volatile("cp.async.commit_group;");
    }

    for (int t = 0; t < nt; t++) {
        asm volatile("cp.async.wait_group %0;" :: "n"(STG - 2));
        __syncthreads();

        int ntile = t + STG - 1;
        if (ntile < nt) HISSUE(ntile, ntile & (STG - 1));
        asm volatile("cp.async.commit_group;");

        const __half* as = (const __half*)(smc + (t & (STG - 1)) * STAGE_B);
        const __half* bs = as + BM * BKH;

#pragma unroll
        for (int kk = 0; kk < 2; kk++) {
            int kb = kk * 16 + 2 * t4;
            uint32_t af[4][4];
#pragma unroll
            for (int i = 0; i < 4; i++) {
                int rr = wm + i * 16 + g8;
                af[i][0] = *(const uint32_t*)(as + rr * BKH + kb);
                af[i][1] = *(const uint32_t*)(as + (rr + 8) * BKH + kb);
                af[i][2] = *(const uint32_t*)(as + rr * BKH + kb + 8);
                af[i][3] = *(const uint32_t*)(as + (rr + 8) * BKH + kb + 8);
            }
#pragma unroll
            for (int j = 0; j < 4; j++) {
                int n0 = wn + j * 8 + g8;
                uint32_t bf0 = *(const uint32_t*)(bs + n0 * BKH + kb);
                uint32_t bf1 = *(const uint32_t*)(bs + n0 * BKH + kb + 8);
#pragma unroll
                for (int i = 0; i < 4; i++) mma_f16(acc[i][j], af[i], bf0, bf1);
            }
        }
    }

    // ---- epilogue ----
    float cs[4][2], cb[4][2], cm[4][2];
    if (mode == 1) {
#pragma unroll
        for (int j = 0; j < 4; j++) {
            int c = tileN + wn + j * 8 + t4 * 2;
#pragma unroll
            for (int q = 0; q < 2; q++) {
                cs[j][q] = gv[c + q] * rsqrtf(vv[c + q] + 1e-5f);
                cb[j][q] = bv[c + q];
                cm[j][q] = mv[c + q];
            }
        }
    }

#pragma unroll
    for (int i = 0; i < 4; i++) {
#pragma unroll
        for (int half8 = 0; half8 < 2; half8++) {
            int r = tileM + wm + i * 16 + g8 + half8 * 8;
            if (r >= M) continue;
#pragma unroll
            for (int j = 0; j < 4; j++) {
                int c = tileN + wn + j * 8 + t4 * 2;
                float v0 = acc[i][j][half8 * 2 + 0];
                float v1 = acc[i][j][half8 * 2 + 1];
                if (mode == 1) {
                    v0 = fmaxf((v0 - cm[j][0]) * cs[j][0] + cb[j][0], 0.f);
                    v1 = fmaxf((v1 - cm[j][1]) * cs[j][1] + cb[j][1], 0.f);
                    __half2 hv;
                    hv.x = __float2half(v0);
                    hv.y = __float2half(v1);
                    *(__half2*)(Ch + (size_t)r * Ncols + c) = hv;
                } else {
                    float* crow = Cf + (size_t)r * Ncols + c;
                    if (accum) {
                        float2 old = *(const float2*)crow;
                        v0 += old.x;
                        v1 += old.y;
                    }
                    *(float2*)crow = make_float2(v0, v1);
                }
            }
        }
    }
}

// ---------------- host orchestration ----------------
extern "C" void kernel_launch(void* const* d_in, const int* in_sizes, int n_in,
                              void* d_out, int out_size) {
    const float* x  = (const float*)d_in[0];
    const int*   ei = (const int*)d_in[1];
    const float* ea = (const float*)d_in[2];
    int base = 3;
    if (n_in > 19) base = 3 + (n_in - 19);
    const float* l0_src  = (const float*)d_in[base + 0];
    const float* l0_dst  = (const float*)d_in[base + 1];
    const float* l0_edge = (const float*)d_in[base + 2];
    const float* l0_w1   = (const float*)d_in[base + 3];
    const float* l0_g    = (const float*)d_in[base + 4];
    const float* l0_b    = (const float*)d_in[base + 5];
    const float* l0_m    = (const float*)d_in[base + 6];
    const float* l0_v    = (const float*)d_in[base + 7];
    const float* l0_w2   = (const float*)d_in[base + 8];
    const float* l1_edge = (const float*)d_in[base + 9];
    const float* l1_w1   = (const float*)d_in[base + 10];
    const float* l1_g    = (const float*)d_in[base + 11];
    const float* l1_b    = (const float*)d_in[base + 12];
    const float* l1_m    = (const float*)d_in[base + 13];
    const float* l1_v    = (const float*)d_in[base + 14];
    const float* l1_w2   = (const float*)d_in[base + 15];
    float* out = (float*)d_out;

    float *sf, *df, *yb, *x1b;
    __half *xh, *ob, *hb, *w0s, *w0d, *w01, *w02, *w11, *w12;
    int *rowptr, *cursor, *eidx;
    cudaGetSymbolAddress((void**)&sf, g_sf);
    cudaGetSymbolAddress((void**)&df, g_df);
    cudaGetSymbolAddress((void**)&yb, g_y);
    cudaGetSymbolAddress((void**)&x1b, g_x1);
    cudaGetSymbolAddress((void**)&xh, g_xh);
    cudaGetSymbolAddress((void**)&ob, g_ob);
    cudaGetSymbolAddress((void**)&hb, g_hb);
    cudaGetSymbolAddress((void**)&w0s, g_w0s);
    cudaGetSymbolAddress((void**)&w0d, g_w0d);
    cudaGetSymbolAddress((void**)&w01, g_w01);
    cudaGetSymbolAddress((void**)&w02, g_w02);
    cudaGetSymbolAddress((void**)&w11, g_w11);
    cudaGetSymbolAddress((void**)&w12, g_w12);
    cudaGetSymbolAddress((void**)&rowptr, g_rowptr);
    cudaGetSymbolAddress((void**)&cursor, g_cursor);
    cudaGetSymbolAddress((void**)&eidx, g_eidx);

    cudaFuncSetAttribute(k_hgemm, cudaFuncAttributeMaxDynamicSharedMemorySize, DSMEM);

    const int offs[2] = {0, LPART};

    // ---- fp16 operand conversion ----
    k_half<<<(NN * FINC + 255) / 256, 256>>>(x, xh, NN * FINC);
    k_half<<<(2 * HC * FINC + 255) / 256, 256>>>(l0_src, w0s, 2 * HC * FINC);
    k_half<<<(2 * HC * FINC + 255) / 256, 256>>>(l0_dst, w0d, 2 * HC * FINC);
    k_half<<<(2 * H2C * HC + 255) / 256, 256>>>(l0_w1, w01, 2 * H2C * HC);
    k_half<<<(2 * HC * H2C + 255) / 256, 256>>>(l0_w2, w02, 2 * HC * H2C);
    k_half<<<(2 * H2C * HC + 255) / 256, 256>>>(l1_w1, w11, 2 * H2C * HC);
    k_half<<<(2 * HC * H2C + 255) / 256, 256>>>(l1_w2, w12, 2 * HC * H2C);

    // ---- CSR build ----
    for (int p = 0; p < 2; p++) {
        int* rp = rowptr + p * (NN + 1);
        int* cu = cursor + p * NN;
        int* ex = eidx + p * LPART;
        const int* dstp = ei + ETOT + offs[p];
        k_zero_int<<<(NN + 255) / 256, 256>>>(cu, NN);
        k_count_deg<<<(LPART + 255) / 256, 256>>>(dstp, LPART, cu);
        k_scan<<<1, 1024>>>(cu, rp, NN);
        k_copy_int<<<(NN + 255) / 256, 256>>>(rp, cu, NN);
        k_scatter<<<(LPART + 255) / 256, 256>>>(dstp, LPART, cu, ex);
        k_sort_buckets<<<(NN + 127) / 128, 128>>>(rp, ex);
    }

    dim3 blk(256);
    int gy = (NN + BM - 1) / BM;  // 157
    dim3 g512(HC / BN, gy), g1024(H2C / BN, gy);

    // ---- layer 0 ----
    for (int l = 0; l < 2; l++) {
        k_hgemm<<<g512, blk, DSMEM>>>(xh, w0s + (size_t)l * HC * FINC,
                                      NN, FINC, HC, 0, nullptr, nullptr, nullptr, nullptr,
                                      sf, nullptr, 0);
        k_hgemm<<<g512, blk, DSMEM>>>(xh, w0d + (size_t)l * HC * FINC,
                                      NN, FINC, HC, 0, nullptr, nullptr, nullptr, nullptr,
                                      df, nullptr, 0);
        k_agg<<<(NN + 3) / 4, 128>>>(sf, df, l0_edge + (size_t)l * HC, ea + offs[l],
                                     ei + offs[l], rowptr + l * (NN + 1),
                                     eidx + l * LPART, ob);
        k_hgemm<<<g1024, blk, DSMEM>>>(ob, w01 + (size_t)l * H2C * HC,
                                       NN, HC, H2C, 1,
                                       l0_g + l * H2C, l0_b + l * H2C,
                                       l0_m + l * H2C, l0_v + l * H2C,
                                       nullptr, hb, 0);
        k_hgemm<<<g512, blk, DSMEM>>>(hb, w02 + (size_t)l * HC * H2C,
                                      NN, H2C, HC, 0, nullptr, nullptr, nullptr, nullptr,
                                      yb, nullptr, l > 0);
    }

    k_leaky<<<(NN * HC + 255) / 256, 256>>>(yb, x1b, NN * HC);

    // ---- layer 1 (sf = df = x1) ----
    for (int l = 0; l < 2; l++) {
        k_agg<<<(NN + 3) / 4, 128>>>(x1b, x1b, l1_edge + (size_t)l * HC, ea + offs[l],
                                     ei + offs[l], rowptr + l * (NN + 1),
                                     eidx + l * LPART, ob);
        k_hgemm<<<g1024, blk, DSMEM>>>(ob, w11 + (size_t)l * H2C * HC,
                                       NN, HC, H2C, 1,
                                       l1_g + l * H2C, l1_b + l * H2C,
                                       l1_m + l * H2C, l1_v + l * H2C,
                                       nullptr, hb, 0);
        k_hgemm<<<g512, blk, DSMEM>>>(hb, w12 + (size_t)l * HC * H2C,
                                      NN, H2C, HC, 0, nullptr, nullptr, nullptr, nullptr,
                                      out, nullptr, l > 0);
    }
}